// round 3
// baseline (speedup 1.0000x reference)
#include <cuda_runtime.h>
#include <cuda_bf16.h>
#include <cstdint>

typedef unsigned long long ull;

#define TT   128
#define BB   64
#define HH   512
#define EE   256
#define VV   5000
#define NSTEP 255          /* 128 enc + 127 dec */
#define NCOLS_E 8192       /* 128*64 */
#define NCOLS_D 8128       /* 127*64 */
#define RNN_CTAS 128

/* ---------------- device scratch (static, no allocation) ---------------- */
__device__ float g_xe[NCOLS_E][EE];          /* gathered enc embeddings [col][e]   */
__device__ float g_xd[NCOLS_D][EE];          /* gathered dec embeddings            */
__device__ float g_pre_e[TT][HH][BB][4];     /* layer0 input preacts (enc)         */
__device__ float g_pre_d[TT - 1][HH][BB][4]; /* layer0 input preacts (dec)         */
__device__ float g_w0e[HH][HH][4];           /* enc Whh0 repacked [u][k][i,f,g,o]  */
__device__ float g_w0d[HH][HH][4];
__device__ float g_w1e[HH][2 * HH][4];       /* [u][k<512:Wih1 | k>=512:Whh1][g]   */
__device__ float g_w1d[HH][2 * HH][4];
__device__ float g_h0[2][HH][BB];            /* transposed h, double buffered      */
__device__ float g_h1[2][HH][BB];
__device__ float g_hist[NCOLS_D][HH];        /* h1 history [dstep*64+b][u]         */
__device__ unsigned g_count;
__device__ unsigned g_phase;

/* ---------------- f32x2 helpers ---------------- */
__device__ __forceinline__ void fma2(ull& acc, ull a, ull b) {
    asm("fma.rn.f32x2 %0, %1, %2, %0;" : "+l"(acc) : "l"(a), "l"(b));
}
__device__ __forceinline__ ull splat2(float x) {
    ull r; unsigned u = __float_as_uint(x);
    asm("mov.b64 %0, {%1, %1};" : "=l"(r) : "r"(u));
    return r;
}
__device__ __forceinline__ float2 unpack2(ull v) {
    unsigned lo, hi;
    asm("mov.b64 {%0, %1}, %2;" : "=r"(lo), "=r"(hi) : "l"(v));
    float2 f; f.x = __uint_as_float(lo); f.y = __uint_as_float(hi);
    return f;
}
__device__ __forceinline__ float sigf(float x) { return 1.0f / (1.0f + __expf(-x)); }

/* ---------------- reset: barrier state, h init, out[t=0]=0 ---------------- */
__global__ void reset_kernel(float* __restrict__ out) {
    int i = blockIdx.x * blockDim.x + threadIdx.x;
    if (i < BB * VV) out[i] = 0.0f;                 /* outputs[0] = zeros */
    if (i < HH * BB) {
        (&g_h0[0][0][0])[i] = 0.0f;                 /* h0 buffer 0 */
        (&g_h1[0][0][0])[i] = 0.0f;                 /* h1 buffer 0 */
    }
    if (i == 0) { g_count = 0u; g_phase = 0u; }
}

/* ---------------- embedding gather: x[col][e] = emb[tok[col]][e] ---------------- */
__global__ void gather_kernel(const float* __restrict__ emb,
                              const int* __restrict__ tok,
                              int ncols, int dec) {
    int i = blockIdx.x * blockDim.x + threadIdx.x;   /* one float4 per thread */
    if (i >= ncols * (EE / 4)) return;
    int col = i >> 6;            /* EE/4 = 64 */
    int e4  = i & 63;
    float4 v = ((const float4*)emb)[(size_t)tok[col] * 64 + e4];
    float4* dst = dec ? (float4*)&g_xd[0][0] : (float4*)&g_xe[0][0];
    dst[(size_t)col * 64 + e4] = v;
}

/* ---------------- weight repack into gate-interleaved float4 ---------------- */
__global__ void repack_kernel(const float* __restrict__ eWhh0, const float* __restrict__ dWhh0,
                              const float* __restrict__ eWih1, const float* __restrict__ eWhh1,
                              const float* __restrict__ dWih1, const float* __restrict__ dWhh1) {
    int stride = gridDim.x * blockDim.x;
    int idx = blockIdx.x * blockDim.x + threadIdx.x;
    for (int i = idx; i < HH * HH; i += stride) {
        int u = i / HH, k = i % HH;
        #pragma unroll
        for (int g = 0; g < 4; g++) {
            g_w0e[u][k][g] = eWhh0[(size_t)(g * HH + u) * HH + k];
            g_w0d[u][k][g] = dWhh0[(size_t)(g * HH + u) * HH + k];
        }
    }
    for (int i = idx; i < HH * 2 * HH; i += stride) {
        int u = i / (2 * HH), k = i % (2 * HH);
        #pragma unroll
        for (int g = 0; g < 4; g++) {
            float ve, vd;
            if (k < HH) { ve = eWih1[(size_t)(g * HH + u) * HH + k];
                          vd = dWih1[(size_t)(g * HH + u) * HH + k]; }
            else        { ve = eWhh1[(size_t)(g * HH + u) * HH + (k - HH)];
                          vd = dWhh1[(size_t)(g * HH + u) * HH + (k - HH)]; }
            g_w1e[u][k][g] = ve;
            g_w1d[u][k][g] = vd;
        }
    }
}

/* ---------------- generic 64x64 tiled fp32 GEMM, C = A(MxK) * B(NxK)^T ----------------
   mode 0: pre-enc epilogue -> g_pre_e (+bias)
   mode 1: pre-dec epilogue -> g_pre_d (+bias)
   mode 2: fc epilogue      -> d_out (+bias, vocab_sim mask)                     */
__global__ void __launch_bounds__(256) gemm_kernel(
    const float* __restrict__ A, int M, int K, int mode,
    const float* __restrict__ bias,
    const int* __restrict__ src, const float* __restrict__ vs,
    float* __restrict__ outp) {
    __shared__ float As[32][64];
    __shared__ float Bs[32][64];

    const float* B = (mode == 0) ? &g_xe[0][0] : (mode == 1) ? &g_xd[0][0] : &g_hist[0][0];

    int tid = threadIdx.x;
    int r = (tid & 15) << 2;       /* row offset in tile   */
    int c = (tid >> 4) << 2;       /* col offset in tile   */
    int m0 = blockIdx.y * 64;
    int n0 = blockIdx.x * 64;

    ull acc[4][2];
    #pragma unroll
    for (int i = 0; i < 4; i++) { acc[i][0] = 0ull; acc[i][1] = 0ull; }

    for (int kt = 0; kt < K; kt += 32) {
        #pragma unroll
        for (int rep = 0; rep < 2; rep++) {
            int f = tid + rep * 256;          /* 0..511 */
            int m = f >> 3;                   /* 0..63  */
            int k4 = (f & 7) << 2;            /* 0..28  */
            int gm = m0 + m;
            float4 va = make_float4(0.f, 0.f, 0.f, 0.f);
            if (gm < M) va = *(const float4*)&A[(size_t)gm * K + kt + k4];
            As[k4 + 0][m] = va.x; As[k4 + 1][m] = va.y;
            As[k4 + 2][m] = va.z; As[k4 + 3][m] = va.w;
            float4 vb = *(const float4*)&B[(size_t)(n0 + m) * K + kt + k4];
            Bs[k4 + 0][m] = vb.x; Bs[k4 + 1][m] = vb.y;
            Bs[k4 + 2][m] = vb.z; Bs[k4 + 3][m] = vb.w;
        }
        __syncthreads();
        #pragma unroll
        for (int k = 0; k < 32; k++) {
            float4 av = *(const float4*)&As[k][r];
            float4 bv = *(const float4*)&Bs[k][c];
            ull b01 = ((const ull*)&bv)[0];
            ull b23 = ((const ull*)&bv)[1];
            ull a0 = splat2(av.x), a1 = splat2(av.y), a2 = splat2(av.z), a3 = splat2(av.w);
            fma2(acc[0][0], a0, b01); fma2(acc[0][1], a0, b23);
            fma2(acc[1][0], a1, b01); fma2(acc[1][1], a1, b23);
            fma2(acc[2][0], a2, b01); fma2(acc[2][1], a2, b23);
            fma2(acc[3][0], a3, b01); fma2(acc[3][1], a3, b23);
        }
        __syncthreads();
    }

    #pragma unroll
    for (int i = 0; i < 4; i++) {
        int m = m0 + r + i;
        if (m >= M) continue;
        float bval = bias[m];
        float2 v01 = unpack2(acc[i][0]);
        float2 v23 = unpack2(acc[i][1]);
        float vals[4] = { v01.x + bval, v01.y + bval, v23.x + bval, v23.y + bval };
        #pragma unroll
        for (int j = 0; j < 4; j++) {
            int n = n0 + c + j;
            if (mode == 2) {
                /* n = dstep*64 + b ; t = dstep+1 ; s0 = src[dstep][b], s1 = src[dstep+1][b] */
                int s0 = src[n], s1 = src[n + 64];
                float sim = fminf(vs[(size_t)s0 * VV + m], vs[(size_t)s1 * VV + m]);
                float md = fminf(sim, 20.0f);
                float mult = (m == 3 || m == 4 || m == VV - 1) ? 1.0f
                                                               : (md * md - 20.0f * md + 1.0f);
                outp[(size_t)(n + 64) * VV + m] = vals[j] * mult;
            } else {
                int t = n >> 6, b = n & 63;
                int uu = m & 511, g = m >> 9;
                float* dst = (mode == 0) ? &g_pre_e[0][0][0][0] : &g_pre_d[0][0][0][0];
                dst[(((size_t)t * HH + uu) * BB + b) * 4 + g] = vals[j];
            }
        }
    }
}

/* ---------------- grid barrier (sense by monotone phase) ---------------- */
__device__ __forceinline__ void grid_barrier(unsigned nctas, unsigned& local_phase) {
    __syncthreads();
    if (threadIdx.x == 0) {
        unsigned target = local_phase + 1u;
        __threadfence();
        unsigned old = atomicAdd(&g_count, 1u);
        if (old == nctas - 1u) {
            g_count = 0u;
            __threadfence();
            atomicExch(&g_phase, target);
        } else {
            while (*(volatile unsigned*)&g_phase < target) { }
            __threadfence();
        }
    }
    local_phase++;
    __syncthreads();
}

/* ---------------- persistent LSTM recurrence ---------------- */
__global__ void __launch_bounds__(128, 1) rnn_kernel(const float* __restrict__ eb1,
                                                     const float* __restrict__ db1) {
    const int tid = threadIdx.x;
    const int lane = tid & 31;
    const int usub = tid >> 5;
    const int u = blockIdx.x * 4 + usub;   /* hidden unit owned by this thread  */
    const int b0 = lane * 2;               /* batch pair (b0, b0+1)             */
    const unsigned nctas = gridDim.x;
    unsigned phase = 0;

    float2 c0 = make_float2(0.f, 0.f);
    float2 c1 = make_float2(0.f, 0.f);

    float be[4], bd[4];
    #pragma unroll
    for (int g = 0; g < 4; g++) { be[g] = eb1[g * HH + u]; bd[g] = db1[g * HH + u]; }

    for (int t = 0; t < NSTEP; t++) {
        const bool enc = (t < TT);

        /* ---- layer 0: gates = pre[t] + Whh0 @ h0old ---- */
        const float4* w0 = (const float4*)(enc ? &g_w0e[u][0][0] : &g_w0d[u][0][0]);
        const float* h0old = &g_h0[t & 1][0][0];
        ull acc0[4] = {0ull, 0ull, 0ull, 0ull};
        #pragma unroll 4
        for (int k = 0; k < HH; k++) {
            ull h2 = *(const ull*)(h0old + (size_t)k * BB + b0);
            float4 w = w0[k];
            fma2(acc0[0], h2, splat2(w.x));
            fma2(acc0[1], h2, splat2(w.y));
            fma2(acc0[2], h2, splat2(w.z));
            fma2(acc0[3], h2, splat2(w.w));
        }
        const float4* pre4 = enc ? (const float4*)&g_pre_e[t][u][0][0]
                                 : (const float4*)&g_pre_d[t - TT][u][0][0];
        float4 p0 = pre4[b0];
        float4 p1 = pre4[b0 + 1];
        float2 zi = unpack2(acc0[0]); zi.x += p0.x; zi.y += p1.x;
        float2 zf = unpack2(acc0[1]); zf.x += p0.y; zf.y += p1.y;
        float2 zg = unpack2(acc0[2]); zg.x += p0.z; zg.y += p1.z;
        float2 zo = unpack2(acc0[3]); zo.x += p0.w; zo.y += p1.w;
        c0.x = sigf(zf.x) * c0.x + sigf(zi.x) * tanhf(zg.x);
        c0.y = sigf(zf.y) * c0.y + sigf(zi.y) * tanhf(zg.y);
        float2 h0n;
        h0n.x = sigf(zo.x) * tanhf(c0.x);
        h0n.y = sigf(zo.y) * tanhf(c0.y);
        float* h0new = &g_h0[(t + 1) & 1][0][0];
        *(float2*)(h0new + (size_t)u * BB + b0) = h0n;

        grid_barrier(nctas, phase);

        /* ---- layer 1: gates = Wih1 @ h0new + Whh1 @ h1old + b1 ---- */
        const float4* w1 = (const float4*)(enc ? &g_w1e[u][0][0] : &g_w1d[u][0][0]);
        const float* h1old = &g_h1[t & 1][0][0];
        ull acc1[4] = {0ull, 0ull, 0ull, 0ull};
        #pragma unroll 4
        for (int k = 0; k < HH; k++) {
            ull h2 = *(const ull*)(h0new + (size_t)k * BB + b0);
            float4 w = w1[k];
            fma2(acc1[0], h2, splat2(w.x));
            fma2(acc1[1], h2, splat2(w.y));
            fma2(acc1[2], h2, splat2(w.z));
            fma2(acc1[3], h2, splat2(w.w));
        }
        #pragma unroll 4
        for (int k = 0; k < HH; k++) {
            ull h2 = *(const ull*)(h1old + (size_t)k * BB + b0);
            float4 w = w1[HH + k];
            fma2(acc1[0], h2, splat2(w.x));
            fma2(acc1[1], h2, splat2(w.y));
            fma2(acc1[2], h2, splat2(w.z));
            fma2(acc1[3], h2, splat2(w.w));
        }
        float bi = enc ? be[0] : bd[0];
        float bf = enc ? be[1] : bd[1];
        float bg = enc ? be[2] : bd[2];
        float bo = enc ? be[3] : bd[3];
        zi = unpack2(acc1[0]); zi.x += bi; zi.y += bi;
        zf = unpack2(acc1[1]); zf.x += bf; zf.y += bf;
        zg = unpack2(acc1[2]); zg.x += bg; zg.y += bg;
        zo = unpack2(acc1[3]); zo.x += bo; zo.y += bo;
        c1.x = sigf(zf.x) * c1.x + sigf(zi.x) * tanhf(zg.x);
        c1.y = sigf(zf.y) * c1.y + sigf(zi.y) * tanhf(zg.y);
        float2 h1n;
        h1n.x = sigf(zo.x) * tanhf(c1.x);
        h1n.y = sigf(zo.y) * tanhf(c1.y);
        *(float2*)(&g_h1[(t + 1) & 1][0][0] + (size_t)u * BB + b0) = h1n;
        if (!enc) {
            int col = (t - TT) * BB + b0;
            g_hist[col][u] = h1n.x;
            g_hist[col + 1][u] = h1n.y;
        }

        grid_barrier(nctas, phase);
    }
}

/* ---------------- launch ---------------- */
extern "C" void kernel_launch(void* const* d_in, const int* in_sizes, int n_in,
                              void* d_out, int out_size) {
    /* skip scalar (size-1) inputs like src_lens/trg_lens regardless of layout */
    const void* in[32];
    int j = 0;
    for (int k = 0; k < n_in && j < 32; k++) {
        if (in_sizes[k] == 1) continue;
        in[j++] = d_in[k];
    }
    const int*   src   = (const int*)in[0];
    const int*   trg   = (const int*)in[1];
    const float* vs    = (const float*)in[2];
    const float* embE  = (const float*)in[3];
    const float* embD  = (const float*)in[4];
    const float* eWih0 = (const float*)in[5];
    const float* eWhh0 = (const float*)in[6];
    const float* eb0   = (const float*)in[7];
    const float* eWih1 = (const float*)in[8];
    const float* eWhh1 = (const float*)in[9];
    const float* eb1   = (const float*)in[10];
    const float* dWih0 = (const float*)in[11];
    const float* dWhh0 = (const float*)in[12];
    const float* db0   = (const float*)in[13];
    const float* dWih1 = (const float*)in[14];
    const float* dWhh1 = (const float*)in[15];
    const float* db1   = (const float*)in[16];
    const float* fcW   = (const float*)in[17];
    const float* fcb   = (const float*)in[18];
    float* out = (float*)d_out;

    reset_kernel<<<1250, 256>>>(out);
    gather_kernel<<<2048, 256>>>(embE, src, NCOLS_E, 0);
    gather_kernel<<<2032, 256>>>(embD, trg, NCOLS_D, 1);
    repack_kernel<<<512, 256>>>(eWhh0, dWhh0, eWih1, eWhh1, dWih1, dWhh1);

    /* layer-0 input preactivations */
    gemm_kernel<<<dim3(NCOLS_E / 64, 2048 / 64), 256>>>(eWih0, 2048, EE, 0, eb0,
                                                        nullptr, nullptr, nullptr);
    gemm_kernel<<<dim3(NCOLS_D / 64, 2048 / 64), 256>>>(dWih0, 2048, EE, 1, db0,
                                                        nullptr, nullptr, nullptr);
    /* serial recurrence */
    rnn_kernel<<<RNN_CTAS, 128>>>(eb1, db1);
    /* vocab projection + similarity mask */
    gemm_kernel<<<dim3(NCOLS_D / 64, (VV + 63) / 64), 256>>>(fcW, VV, HH, 2, fcb,
                                                             src, vs, out);
}

// round 4
// speedup vs baseline: 2.3871x; 2.3871x over previous
#include <cuda_runtime.h>
#include <cuda_bf16.h>
#include <cstdint>

typedef unsigned long long ull;

#define TT   128
#define BB   64
#define HH   512
#define EE   256
#define VV   5000
#define NSTEP 255          /* 128 enc + 127 dec */
#define NCOLS_E 8192       /* 128*64 */
#define NCOLS_D 8128       /* 127*64 */
#define RNN_CTAS 128
#define W_SMEM_FLOATS 24576      /* w0: 4*512*4 = 8192 ; w1: 4*1024*4 = 16384 */
#define W_SMEM_BYTES  (W_SMEM_FLOATS * 4)

/* ---------------- device scratch (static, no allocation) ---------------- */
__device__ float g_xe[NCOLS_E][EE];          /* gathered enc embeddings [col][e]   */
__device__ float g_xd[NCOLS_D][EE];          /* gathered dec embeddings            */
__device__ float g_pre_e[TT][HH][BB][4];     /* layer0 input preacts (enc)         */
__device__ float g_pre_d[TT - 1][HH][BB][4]; /* layer0 input preacts (dec)         */
__device__ float g_w0e[HH][HH][4];           /* enc Whh0 repacked [u][k][i,f,g,o]  */
__device__ float g_w0d[HH][HH][4];
__device__ float g_w1e[HH][2 * HH][4];       /* [u][k<512:Wih1 | k>=512:Whh1][g]   */
__device__ float g_w1d[HH][2 * HH][4];
__device__ float g_h0[2][HH][BB];            /* transposed h, double buffered      */
__device__ float g_h1[2][HH][BB];
__device__ float g_hist[NCOLS_D][HH];        /* h1 history [dstep*64+b][u]         */
__device__ unsigned g_count;
__device__ unsigned g_phase;

/* ---------------- f32x2 helpers ---------------- */
__device__ __forceinline__ void fma2(ull& acc, ull a, ull b) {
    asm("fma.rn.f32x2 %0, %1, %2, %0;" : "+l"(acc) : "l"(a), "l"(b));
}
__device__ __forceinline__ ull splat2(float x) {
    ull r; unsigned u = __float_as_uint(x);
    asm("mov.b64 %0, {%1, %1};" : "=l"(r) : "r"(u));
    return r;
}
__device__ __forceinline__ float2 unpack2(ull v) {
    unsigned lo, hi;
    asm("mov.b64 {%0, %1}, %2;" : "=r"(lo), "=r"(hi) : "l"(v));
    float2 f; f.x = __uint_as_float(lo); f.y = __uint_as_float(hi);
    return f;
}
__device__ __forceinline__ float sigf(float x) { return 1.0f / (1.0f + __expf(-x)); }

/* ---------------- reset: barrier state, h init, out[t=0]=0 ---------------- */
__global__ void reset_kernel(float* __restrict__ out) {
    int i = blockIdx.x * blockDim.x + threadIdx.x;
    if (i < BB * VV) out[i] = 0.0f;                 /* outputs[0] = zeros */
    if (i < HH * BB) {
        (&g_h0[0][0][0])[i] = 0.0f;
        (&g_h1[0][0][0])[i] = 0.0f;
    }
    if (i == 0) { g_count = 0u; g_phase = 0u; }
}

/* ---------------- embedding gather ---------------- */
__global__ void gather_kernel(const float* __restrict__ emb,
                              const int* __restrict__ tok,
                              int ncols, int dec) {
    int i = blockIdx.x * blockDim.x + threadIdx.x;   /* one float4 per thread */
    if (i >= ncols * (EE / 4)) return;
    int col = i >> 6;            /* EE/4 = 64 */
    int e4  = i & 63;
    float4 v = ((const float4*)emb)[(size_t)tok[col] * 64 + e4];
    float4* dst = dec ? (float4*)&g_xd[0][0] : (float4*)&g_xe[0][0];
    dst[(size_t)col * 64 + e4] = v;
}

/* ---------------- weight repack into gate-interleaved float4 ---------------- */
__global__ void repack_kernel(const float* __restrict__ eWhh0, const float* __restrict__ dWhh0,
                              const float* __restrict__ eWih1, const float* __restrict__ eWhh1,
                              const float* __restrict__ dWih1, const float* __restrict__ dWhh1) {
    int stride = gridDim.x * blockDim.x;
    int idx = blockIdx.x * blockDim.x + threadIdx.x;
    for (int i = idx; i < HH * HH; i += stride) {
        int u = i / HH, k = i % HH;
        #pragma unroll
        for (int g = 0; g < 4; g++) {
            g_w0e[u][k][g] = eWhh0[(size_t)(g * HH + u) * HH + k];
            g_w0d[u][k][g] = dWhh0[(size_t)(g * HH + u) * HH + k];
        }
    }
    for (int i = idx; i < HH * 2 * HH; i += stride) {
        int u = i / (2 * HH), k = i % (2 * HH);
        #pragma unroll
        for (int g = 0; g < 4; g++) {
            float ve, vd;
            if (k < HH) { ve = eWih1[(size_t)(g * HH + u) * HH + k];
                          vd = dWih1[(size_t)(g * HH + u) * HH + k]; }
            else        { ve = eWhh1[(size_t)(g * HH + u) * HH + (k - HH)];
                          vd = dWhh1[(size_t)(g * HH + u) * HH + (k - HH)]; }
            g_w1e[u][k][g] = ve;
            g_w1d[u][k][g] = vd;
        }
    }
}

/* ---------------- generic 64x64 tiled fp32 GEMM, C = A(MxK) * B(NxK)^T ----------------
   mode 0: pre-enc epilogue -> g_pre_e (+bias)
   mode 1: pre-dec epilogue -> g_pre_d (+bias)
   mode 2: fc epilogue      -> d_out (+bias, vocab_sim mask)                     */
__global__ void __launch_bounds__(256) gemm_kernel(
    const float* __restrict__ A, int M, int K, int mode,
    const float* __restrict__ bias,
    const int* __restrict__ src, const float* __restrict__ vs,
    float* __restrict__ outp) {
    __shared__ float As[32][64];
    __shared__ float Bs[32][64];

    const float* B = (mode == 0) ? &g_xe[0][0] : (mode == 1) ? &g_xd[0][0] : &g_hist[0][0];

    int tid = threadIdx.x;
    int r = (tid & 15) << 2;
    int c = (tid >> 4) << 2;
    int m0 = blockIdx.y * 64;
    int n0 = blockIdx.x * 64;

    ull acc[4][2];
    #pragma unroll
    for (int i = 0; i < 4; i++) { acc[i][0] = 0ull; acc[i][1] = 0ull; }

    for (int kt = 0; kt < K; kt += 32) {
        #pragma unroll
        for (int rep = 0; rep < 2; rep++) {
            int f = tid + rep * 256;
            int m = f >> 3;
            int k4 = (f & 7) << 2;
            int gm = m0 + m;
            float4 va = make_float4(0.f, 0.f, 0.f, 0.f);
            if (gm < M) va = *(const float4*)&A[(size_t)gm * K + kt + k4];
            As[k4 + 0][m] = va.x; As[k4 + 1][m] = va.y;
            As[k4 + 2][m] = va.z; As[k4 + 3][m] = va.w;
            float4 vb = *(const float4*)&B[(size_t)(n0 + m) * K + kt + k4];
            Bs[k4 + 0][m] = vb.x; Bs[k4 + 1][m] = vb.y;
            Bs[k4 + 2][m] = vb.z; Bs[k4 + 3][m] = vb.w;
        }
        __syncthreads();
        #pragma unroll
        for (int k = 0; k < 32; k++) {
            float4 av = *(const float4*)&As[k][r];
            float4 bv = *(const float4*)&Bs[k][c];
            ull b01 = ((const ull*)&bv)[0];
            ull b23 = ((const ull*)&bv)[1];
            ull a0 = splat2(av.x), a1 = splat2(av.y), a2 = splat2(av.z), a3 = splat2(av.w);
            fma2(acc[0][0], a0, b01); fma2(acc[0][1], a0, b23);
            fma2(acc[1][0], a1, b01); fma2(acc[1][1], a1, b23);
            fma2(acc[2][0], a2, b01); fma2(acc[2][1], a2, b23);
            fma2(acc[3][0], a3, b01); fma2(acc[3][1], a3, b23);
        }
        __syncthreads();
    }

    #pragma unroll
    for (int i = 0; i < 4; i++) {
        int m = m0 + r + i;
        if (m >= M) continue;
        float bval = bias[m];
        float2 v01 = unpack2(acc[i][0]);
        float2 v23 = unpack2(acc[i][1]);
        float vals[4] = { v01.x + bval, v01.y + bval, v23.x + bval, v23.y + bval };
        #pragma unroll
        for (int j = 0; j < 4; j++) {
            int n = n0 + c + j;
            if (mode == 2) {
                int s0 = src[n], s1 = src[n + 64];
                float sim = fminf(vs[(size_t)s0 * VV + m], vs[(size_t)s1 * VV + m]);
                float md = fminf(sim, 20.0f);
                float mult = (m == 3 || m == 4 || m == VV - 1) ? 1.0f
                                                               : (md * md - 20.0f * md + 1.0f);
                outp[(size_t)(n + 64) * VV + m] = vals[j] * mult;
            } else {
                int t = n >> 6, b = n & 63;
                int uu = m & 511, g = m >> 9;
                float* dst = (mode == 0) ? &g_pre_e[0][0][0][0] : &g_pre_d[0][0][0][0];
                dst[(((size_t)t * HH + uu) * BB + b) * 4 + g] = vals[j];
            }
        }
    }
}

/* ---------------- grid barrier (sense by monotone phase) ---------------- */
__device__ __forceinline__ void grid_barrier(unsigned nctas, unsigned& local_phase) {
    __syncthreads();
    if (threadIdx.x == 0) {
        unsigned target = local_phase + 1u;
        __threadfence();
        unsigned old = atomicAdd(&g_count, 1u);
        if (old == nctas - 1u) {
            g_count = 0u;
            __threadfence();
            atomicExch(&g_phase, target);
        } else {
            while (*(volatile unsigned*)&g_phase < target) { }
            __threadfence();
        }
    }
    local_phase++;
    __syncthreads();
}

/* ---------------- persistent LSTM recurrence (weights in smem) ---------------- */
__global__ void __launch_bounds__(128, 1) rnn_kernel(const float* __restrict__ eb1,
                                                     const float* __restrict__ db1) {
    extern __shared__ float s_w[];          /* [0,8192): w0 ; [8192,24576): w1 */
    const int tid = threadIdx.x;
    const int lane = tid & 31;
    const int usub = tid >> 5;
    const int u = blockIdx.x * 4 + usub;    /* hidden unit owned by this warp   */
    const int b0 = lane * 2;                /* batch pair (b0, b0+1)            */
    const unsigned nctas = gridDim.x;
    unsigned phase = 0;

    float2 c0 = make_float2(0.f, 0.f);
    float2 c1 = make_float2(0.f, 0.f);

    float be[4], bd[4];
    #pragma unroll
    for (int g = 0; g < 4; g++) { be[g] = eb1[g * HH + u]; bd[g] = db1[g * HH + u]; }

    /* per-warp smem weight views: gate-pair ulls {i,f},{g,o} per k */
    const ulonglong2* w0s = (const ulonglong2*)&s_w[usub * 2048];          /* [512]  */
    const ulonglong2* w1s = (const ulonglong2*)&s_w[8192 + usub * 4096];   /* [1024] */

    for (int t = 0; t < NSTEP; t++) {
        const bool enc = (t < TT);

        /* (re)load weights into smem at t=0 (enc) and t=TT (dec swap) */
        if (t == 0 || t == TT) {
            const float4* src0 = (const float4*)(enc ? &g_w0e[blockIdx.x * 4][0][0]
                                                     : &g_w0d[blockIdx.x * 4][0][0]);
            const float4* src1 = (const float4*)(enc ? &g_w1e[blockIdx.x * 4][0][0]
                                                     : &g_w1d[blockIdx.x * 4][0][0]);
            float4* d0 = (float4*)s_w;
            float4* d1 = (float4*)(s_w + 8192);
            for (int i = tid; i < 2048; i += 128) d0[i] = src0[i];
            for (int i = tid; i < 4096; i += 128) d1[i] = src1[i];
            __syncthreads();
        }

        /* ---- layer 0: gates = pre[t] + Whh0 @ h0old ---- */
        const float* h0old = &g_h0[t & 1][0][0];
        ull aif0 = 0ull, ago0 = 0ull, aif1 = 0ull, ago1 = 0ull;
        for (int k = 0; k < HH; k += 16) {
            float2 hx[16];
            #pragma unroll
            for (int i = 0; i < 16; i++)
                hx[i] = *(const float2*)(h0old + (size_t)(k + i) * BB + b0);
            #pragma unroll
            for (int i = 0; i < 16; i++) {
                ulonglong2 w = w0s[k + i];
                ull ha = splat2(hx[i].x), hb = splat2(hx[i].y);
                fma2(aif0, ha, w.x); fma2(ago0, ha, w.y);
                fma2(aif1, hb, w.x); fma2(ago1, hb, w.y);
            }
        }
        const float4* pre4 = enc ? (const float4*)&g_pre_e[t][u][0][0]
                                 : (const float4*)&g_pre_d[t - TT][u][0][0];
        float4 p0 = pre4[b0];
        float4 p1 = pre4[b0 + 1];
        {
            float2 if0 = unpack2(aif0), go0 = unpack2(ago0);
            float2 if1 = unpack2(aif1), go1 = unpack2(ago1);
            float zi0 = if0.x + p0.x, zf0 = if0.y + p0.y, zg0 = go0.x + p0.z, zo0 = go0.y + p0.w;
            float zi1 = if1.x + p1.x, zf1 = if1.y + p1.y, zg1 = go1.x + p1.z, zo1 = go1.y + p1.w;
            c0.x = sigf(zf0) * c0.x + sigf(zi0) * tanhf(zg0);
            c0.y = sigf(zf1) * c0.y + sigf(zi1) * tanhf(zg1);
            float2 h0n;
            h0n.x = sigf(zo0) * tanhf(c0.x);
            h0n.y = sigf(zo1) * tanhf(c0.y);
            *(float2*)(&g_h0[(t + 1) & 1][0][0] + (size_t)u * BB + b0) = h0n;
        }

        /* single grid barrier per step (double buffering covers all other hazards) */
        grid_barrier(nctas, phase);

        /* ---- layer 1: gates = Wih1 @ h0new + Whh1 @ h1old + b1 ---- */
        const float* h0new = &g_h0[(t + 1) & 1][0][0];
        const float* h1old = &g_h1[t & 1][0][0];
        aif0 = 0ull; ago0 = 0ull; aif1 = 0ull; ago1 = 0ull;
        for (int k = 0; k < HH; k += 16) {
            float2 hx[16];
            #pragma unroll
            for (int i = 0; i < 16; i++)
                hx[i] = *(const float2*)(h0new + (size_t)(k + i) * BB + b0);
            #pragma unroll
            for (int i = 0; i < 16; i++) {
                ulonglong2 w = w1s[k + i];
                ull ha = splat2(hx[i].x), hb = splat2(hx[i].y);
                fma2(aif0, ha, w.x); fma2(ago0, ha, w.y);
                fma2(aif1, hb, w.x); fma2(ago1, hb, w.y);
            }
        }
        for (int k = 0; k < HH; k += 16) {
            float2 hx[16];
            #pragma unroll
            for (int i = 0; i < 16; i++)
                hx[i] = *(const float2*)(h1old + (size_t)(k + i) * BB + b0);
            #pragma unroll
            for (int i = 0; i < 16; i++) {
                ulonglong2 w = w1s[HH + k + i];
                ull ha = splat2(hx[i].x), hb = splat2(hx[i].y);
                fma2(aif0, ha, w.x); fma2(ago0, ha, w.y);
                fma2(aif1, hb, w.x); fma2(ago1, hb, w.y);
            }
        }
        {
            float bi = enc ? be[0] : bd[0];
            float bf = enc ? be[1] : bd[1];
            float bg = enc ? be[2] : bd[2];
            float bo = enc ? be[3] : bd[3];
            float2 if0 = unpack2(aif0), go0 = unpack2(ago0);
            float2 if1 = unpack2(aif1), go1 = unpack2(ago1);
            float zi0 = if0.x + bi, zf0 = if0.y + bf, zg0 = go0.x + bg, zo0 = go0.y + bo;
            float zi1 = if1.x + bi, zf1 = if1.y + bf, zg1 = go1.x + bg, zo1 = go1.y + bo;
            c1.x = sigf(zf0) * c1.x + sigf(zi0) * tanhf(zg0);
            c1.y = sigf(zf1) * c1.y + sigf(zi1) * tanhf(zg1);
            float2 h1n;
            h1n.x = sigf(zo0) * tanhf(c1.x);
            h1n.y = sigf(zo1) * tanhf(c1.y);
            *(float2*)(&g_h1[(t + 1) & 1][0][0] + (size_t)u * BB + b0) = h1n;
            if (!enc) {
                int col = (t - TT) * BB + b0;
                g_hist[col][u] = h1n.x;
                g_hist[col + 1][u] = h1n.y;
            }
        }
        /* no second barrier: L1(t) writes are protected by barrier inside step t+1 */
    }
}

/* ---------------- launch ---------------- */
extern "C" void kernel_launch(void* const* d_in, const int* in_sizes, int n_in,
                              void* d_out, int out_size) {
    const void* in[32];
    int j = 0;
    for (int k = 0; k < n_in && j < 32; k++) {
        if (in_sizes[k] == 1) continue;       /* skip scalar src_lens/trg_lens */
        in[j++] = d_in[k];
    }
    const int*   src   = (const int*)in[0];
    const int*   trg   = (const int*)in[1];
    const float* vs    = (const float*)in[2];
    const float* embE  = (const float*)in[3];
    const float* embD  = (const float*)in[4];
    const float* eWih0 = (const float*)in[5];
    const float* eWhh0 = (const float*)in[6];
    const float* eb0   = (const float*)in[7];
    const float* eWih1 = (const float*)in[8];
    const float* eWhh1 = (const float*)in[9];
    const float* eb1   = (const float*)in[10];
    const float* dWih0 = (const float*)in[11];
    const float* dWhh0 = (const float*)in[12];
    const float* db0   = (const float*)in[13];
    const float* dWih1 = (const float*)in[14];
    const float* dWhh1 = (const float*)in[15];
    const float* db1   = (const float*)in[16];
    const float* fcW   = (const float*)in[17];
    const float* fcb   = (const float*)in[18];
    float* out = (float*)d_out;

    static int smem_set = 0;
    if (!smem_set) {
        cudaFuncSetAttribute(rnn_kernel, cudaFuncAttributeMaxDynamicSharedMemorySize,
                             W_SMEM_BYTES);
        smem_set = 1;
    }

    reset_kernel<<<1250, 256>>>(out);
    gather_kernel<<<2048, 256>>>(embE, src, NCOLS_E, 0);
    gather_kernel<<<2032, 256>>>(embD, trg, NCOLS_D, 1);
    repack_kernel<<<512, 256>>>(eWhh0, dWhh0, eWih1, eWhh1, dWih1, dWhh1);

    /* layer-0 input preactivations */
    gemm_kernel<<<dim3(NCOLS_E / 64, 2048 / 64), 256>>>(eWih0, 2048, EE, 0, eb0,
                                                        nullptr, nullptr, nullptr);
    gemm_kernel<<<dim3(NCOLS_D / 64, 2048 / 64), 256>>>(dWih0, 2048, EE, 1, db0,
                                                        nullptr, nullptr, nullptr);
    /* serial recurrence */
    rnn_kernel<<<RNN_CTAS, 128, W_SMEM_BYTES>>>(eb1, db1);
    /* vocab projection + similarity mask */
    gemm_kernel<<<dim3(NCOLS_D / 64, (VV + 63) / 64), 256>>>(fcW, VV, HH, 2, fcb,
                                                             src, vs, out);
}

// round 5
// speedup vs baseline: 2.5750x; 1.0787x over previous
#include <cuda_runtime.h>
#include <cuda_bf16.h>
#include <cstdint>

typedef unsigned long long ull;

#define TT   128
#define BB   64
#define HH   512
#define EE   256
#define VV   5000
#define NSTEP 255          /* 128 enc + 127 dec */
#define NCOLS_E 8192       /* 128*64 */
#define NCOLS_D 8128       /* 127*64 */
#define RNN_CTAS 128
#define W_SMEM_FLOATS 24576      /* w0: 4*512*4 = 8192 ; w1: 4*1024*4 = 16384 */
#define W_SMEM_BYTES  (W_SMEM_FLOATS * 4)

/* ---------------- device scratch (static, no allocation) ---------------- */
__device__ float g_xe[NCOLS_E][EE];          /* gathered enc embeddings [col][e]   */
__device__ float g_xd[NCOLS_D][EE];          /* gathered dec embeddings            */
__device__ float g_pre_e[TT][HH][BB][4];     /* layer0 input preacts (enc)         */
__device__ float g_pre_d[TT - 1][HH][BB][4]; /* layer0 input preacts (dec)         */
__device__ float g_w0e[HH][HH][4];           /* enc Whh0 repacked [u][k][i,f,g,o]  */
__device__ float g_w0d[HH][HH][4];
__device__ float g_w1e[HH][2 * HH][4];       /* [u][k<512:Wih1 | k>=512:Whh1][g]   */
__device__ float g_w1d[HH][2 * HH][4];
__device__ float g_h0[2][HH][BB];            /* transposed h, double buffered      */
__device__ float g_h1[2][HH][BB];
__device__ float g_hist[NCOLS_D][HH];        /* h1 history [dstep*64+b][u]         */
__device__ unsigned g_count;
__device__ unsigned g_phase;

/* ---------------- f32x2 helpers ---------------- */
__device__ __forceinline__ void fma2(ull& acc, ull a, ull b) {
    asm("fma.rn.f32x2 %0, %1, %2, %0;" : "+l"(acc) : "l"(a), "l"(b));
}
__device__ __forceinline__ ull splat2(float x) {
    ull r; unsigned u = __float_as_uint(x);
    asm("mov.b64 %0, {%1, %1};" : "=l"(r) : "r"(u));
    return r;
}
__device__ __forceinline__ float2 unpack2(ull v) {
    unsigned lo, hi;
    asm("mov.b64 {%0, %1}, %2;" : "=r"(lo), "=r"(hi) : "l"(v));
    float2 f; f.x = __uint_as_float(lo); f.y = __uint_as_float(hi);
    return f;
}
__device__ __forceinline__ float sigf(float x) { return 1.0f / (1.0f + __expf(-x)); }

/* ---------------- reset ---------------- */
__global__ void reset_kernel(float* __restrict__ out) {
    int i = blockIdx.x * blockDim.x + threadIdx.x;
    if (i < BB * VV) out[i] = 0.0f;                 /* outputs[0] = zeros */
    if (i < HH * BB) {
        (&g_h0[0][0][0])[i] = 0.0f;
        (&g_h1[0][0][0])[i] = 0.0f;
    }
    if (i == 0) { g_count = 0u; g_phase = 0u; }
}

/* ---------------- embedding gather ---------------- */
__global__ void gather_kernel(const float* __restrict__ emb,
                              const int* __restrict__ tok,
                              int ncols, int dec) {
    int i = blockIdx.x * blockDim.x + threadIdx.x;   /* one float4 per thread */
    if (i >= ncols * (EE / 4)) return;
    int col = i >> 6;            /* EE/4 = 64 */
    int e4  = i & 63;
    float4 v = ((const float4*)emb)[(size_t)tok[col] * 64 + e4];
    float4* dst = dec ? (float4*)&g_xd[0][0] : (float4*)&g_xe[0][0];
    dst[(size_t)col * 64 + e4] = v;
}

/* ---------------- weight repack into gate-interleaved float4 ---------------- */
__global__ void repack_kernel(const float* __restrict__ eWhh0, const float* __restrict__ dWhh0,
                              const float* __restrict__ eWih1, const float* __restrict__ eWhh1,
                              const float* __restrict__ dWih1, const float* __restrict__ dWhh1) {
    int stride = gridDim.x * blockDim.x;
    int idx = blockIdx.x * blockDim.x + threadIdx.x;
    for (int i = idx; i < HH * HH; i += stride) {
        int u = i / HH, k = i % HH;
        #pragma unroll
        for (int g = 0; g < 4; g++) {
            g_w0e[u][k][g] = eWhh0[(size_t)(g * HH + u) * HH + k];
            g_w0d[u][k][g] = dWhh0[(size_t)(g * HH + u) * HH + k];
        }
    }
    for (int i = idx; i < HH * 2 * HH; i += stride) {
        int u = i / (2 * HH), k = i % (2 * HH);
        #pragma unroll
        for (int g = 0; g < 4; g++) {
            float ve, vd;
            if (k < HH) { ve = eWih1[(size_t)(g * HH + u) * HH + k];
                          vd = dWih1[(size_t)(g * HH + u) * HH + k]; }
            else        { ve = eWhh1[(size_t)(g * HH + u) * HH + (k - HH)];
                          vd = dWhh1[(size_t)(g * HH + u) * HH + (k - HH)]; }
            g_w1e[u][k][g] = ve;
            g_w1d[u][k][g] = vd;
        }
    }
}

/* ---------------- generic 64x64 tiled fp32 GEMM, C = A(MxK) * B(NxK)^T ---------------- */
__global__ void __launch_bounds__(256) gemm_kernel(
    const float* __restrict__ A, int M, int K, int mode,
    const float* __restrict__ bias,
    const int* __restrict__ src, const float* __restrict__ vs,
    float* __restrict__ outp) {
    __shared__ float As[32][64];
    __shared__ float Bs[32][64];

    const float* B = (mode == 0) ? &g_xe[0][0] : (mode == 1) ? &g_xd[0][0] : &g_hist[0][0];

    int tid = threadIdx.x;
    int r = (tid & 15) << 2;
    int c = (tid >> 4) << 2;
    int m0 = blockIdx.y * 64;
    int n0 = blockIdx.x * 64;

    ull acc[4][2];
    #pragma unroll
    for (int i = 0; i < 4; i++) { acc[i][0] = 0ull; acc[i][1] = 0ull; }

    for (int kt = 0; kt < K; kt += 32) {
        #pragma unroll
        for (int rep = 0; rep < 2; rep++) {
            int f = tid + rep * 256;
            int m = f >> 3;
            int k4 = (f & 7) << 2;
            int gm = m0 + m;
            float4 va = make_float4(0.f, 0.f, 0.f, 0.f);
            if (gm < M) va = *(const float4*)&A[(size_t)gm * K + kt + k4];
            As[k4 + 0][m] = va.x; As[k4 + 1][m] = va.y;
            As[k4 + 2][m] = va.z; As[k4 + 3][m] = va.w;
            float4 vb = *(const float4*)&B[(size_t)(n0 + m) * K + kt + k4];
            Bs[k4 + 0][m] = vb.x; Bs[k4 + 1][m] = vb.y;
            Bs[k4 + 2][m] = vb.z; Bs[k4 + 3][m] = vb.w;
        }
        __syncthreads();
        #pragma unroll
        for (int k = 0; k < 32; k++) {
            float4 av = *(const float4*)&As[k][r];
            float4 bv = *(const float4*)&Bs[k][c];
            ull b01 = ((const ull*)&bv)[0];
            ull b23 = ((const ull*)&bv)[1];
            ull a0 = splat2(av.x), a1 = splat2(av.y), a2 = splat2(av.z), a3 = splat2(av.w);
            fma2(acc[0][0], a0, b01); fma2(acc[0][1], a0, b23);
            fma2(acc[1][0], a1, b01); fma2(acc[1][1], a1, b23);
            fma2(acc[2][0], a2, b01); fma2(acc[2][1], a2, b23);
            fma2(acc[3][0], a3, b01); fma2(acc[3][1], a3, b23);
        }
        __syncthreads();
    }

    #pragma unroll
    for (int i = 0; i < 4; i++) {
        int m = m0 + r + i;
        if (m >= M) continue;
        float bval = bias[m];
        float2 v01 = unpack2(acc[i][0]);
        float2 v23 = unpack2(acc[i][1]);
        float vals[4] = { v01.x + bval, v01.y + bval, v23.x + bval, v23.y + bval };
        #pragma unroll
        for (int j = 0; j < 4; j++) {
            int n = n0 + c + j;
            if (mode == 2) {
                int s0 = src[n], s1 = src[n + 64];
                float sim = fminf(vs[(size_t)s0 * VV + m], vs[(size_t)s1 * VV + m]);
                float md = fminf(sim, 20.0f);
                float mult = (m == 3 || m == 4 || m == VV - 1) ? 1.0f
                                                               : (md * md - 20.0f * md + 1.0f);
                outp[(size_t)(n + 64) * VV + m] = vals[j] * mult;
            } else {
                int t = n >> 6, b = n & 63;
                int uu = m & 511, g = m >> 9;
                float* dst = (mode == 0) ? &g_pre_e[0][0][0][0] : &g_pre_d[0][0][0][0];
                dst[(((size_t)t * HH + uu) * BB + b) * 4 + g] = vals[j];
            }
        }
    }
}

/* ---------------- grid barrier (sense by monotone phase) ---------------- */
__device__ __forceinline__ void grid_barrier(unsigned nctas, unsigned& local_phase) {
    __syncthreads();
    if (threadIdx.x == 0) {
        unsigned target = local_phase + 1u;
        __threadfence();
        unsigned old = atomicAdd(&g_count, 1u);
        if (old == nctas - 1u) {
            g_count = 0u;
            __threadfence();
            atomicExch(&g_phase, target);
        } else {
            while (*(volatile unsigned*)&g_phase < target) { }
            __threadfence();
        }
    }
    local_phase++;
    __syncthreads();
}

/* ---------------- software-pipelined GEMV pass over 512 k ----------------
   h layout: hbase points at h[0][b0]; stride BB floats per k.
   Weights: wbase[k] = {i,f} / {g,o} gate pairs (ulonglong2 in smem).
   Double-buffered 16-deep register chunks: chunk i+1's loads issue before
   chunk i's 64 fma2 (~256 cyc), covering L2 latency.                     */
__device__ __forceinline__ void gemv_pass(const float* __restrict__ hbase,
                                          const ulonglong2* __restrict__ wbase,
                                          ull& aif0, ull& ago0, ull& aif1, ull& ago1) {
    float2 bufA[16], bufB[16];
    #pragma unroll
    for (int i = 0; i < 16; i++)
        bufA[i] = *(const float2*)(hbase + (size_t)i * BB);

    #pragma unroll 1
    for (int k = 0; k < HH; k += 32) {
        #pragma unroll
        for (int i = 0; i < 16; i++)
            bufB[i] = *(const float2*)(hbase + (size_t)(k + 16 + i) * BB);
        #pragma unroll
        for (int i = 0; i < 16; i++) {
            ulonglong2 w = wbase[k + i];
            ull ha = splat2(bufA[i].x), hb = splat2(bufA[i].y);
            fma2(aif0, ha, w.x); fma2(ago0, ha, w.y);
            fma2(aif1, hb, w.x); fma2(ago1, hb, w.y);
        }
        int kn = (k + 32 < HH) ? (k + 32) : 0;   /* harmless wrap prefetch */
        #pragma unroll
        for (int i = 0; i < 16; i++)
            bufA[i] = *(const float2*)(hbase + (size_t)(kn + i) * BB);
        #pragma unroll
        for (int i = 0; i < 16; i++) {
            ulonglong2 w = wbase[k + 16 + i];
            ull ha = splat2(bufB[i].x), hb = splat2(bufB[i].y);
            fma2(aif0, ha, w.x); fma2(ago0, ha, w.y);
            fma2(aif1, hb, w.x); fma2(ago1, hb, w.y);
        }
    }
}

/* ---------------- persistent LSTM recurrence (weights in smem) ---------------- */
__global__ void __launch_bounds__(128, 1) rnn_kernel(const float* __restrict__ eb1,
                                                     const float* __restrict__ db1) {
    extern __shared__ float s_w[];          /* [0,8192): w0 ; [8192,24576): w1 */
    const int tid = threadIdx.x;
    const int lane = tid & 31;
    const int usub = tid >> 5;
    const int u = blockIdx.x * 4 + usub;    /* hidden unit owned by this warp   */
    const int b0 = lane * 2;                /* batch pair (b0, b0+1)            */
    const unsigned nctas = gridDim.x;
    unsigned phase = 0;

    float2 c0 = make_float2(0.f, 0.f);
    float2 c1 = make_float2(0.f, 0.f);

    float be[4], bd[4];
    #pragma unroll
    for (int g = 0; g < 4; g++) { be[g] = eb1[g * HH + u]; bd[g] = db1[g * HH + u]; }

    const ulonglong2* w0s = (const ulonglong2*)&s_w[usub * 2048];          /* [512]  */
    const ulonglong2* w1s = (const ulonglong2*)&s_w[8192 + usub * 4096];   /* [1024] */

    for (int t = 0; t < NSTEP; t++) {
        const bool enc = (t < TT);

        /* (re)load weights into smem at t=0 and at the enc->dec swap */
        if (t == 0 || t == TT) {
            const float4* src0 = (const float4*)(enc ? &g_w0e[blockIdx.x * 4][0][0]
                                                     : &g_w0d[blockIdx.x * 4][0][0]);
            const float4* src1 = (const float4*)(enc ? &g_w1e[blockIdx.x * 4][0][0]
                                                     : &g_w1d[blockIdx.x * 4][0][0]);
            float4* d0 = (float4*)s_w;
            float4* d1 = (float4*)(s_w + 8192);
            for (int i = tid; i < 2048; i += 128) d0[i] = src0[i];
            for (int i = tid; i < 4096; i += 128) d1[i] = src1[i];
            __syncthreads();
        }

        /* hoist pre-activation loads: independent of everything below */
        const float4* pre4 = enc ? (const float4*)&g_pre_e[t][u][0][0]
                                 : (const float4*)&g_pre_d[t - TT][u][0][0];
        float4 p0 = pre4[b0];
        float4 p1 = pre4[b0 + 1];

        /* ---- layer 0: gates = pre[t] + Whh0 @ h0old ---- */
        const float* h0old = &g_h0[t & 1][0][0] + b0;
        ull aif0 = 0ull, ago0 = 0ull, aif1 = 0ull, ago1 = 0ull;
        gemv_pass(h0old, w0s, aif0, ago0, aif1, ago1);
        {
            float2 if0 = unpack2(aif0), go0 = unpack2(ago0);
            float2 if1 = unpack2(aif1), go1 = unpack2(ago1);
            float zi0 = if0.x + p0.x, zf0 = if0.y + p0.y, zg0 = go0.x + p0.z, zo0 = go0.y + p0.w;
            float zi1 = if1.x + p1.x, zf1 = if1.y + p1.y, zg1 = go1.x + p1.z, zo1 = go1.y + p1.w;
            c0.x = sigf(zf0) * c0.x + sigf(zi0) * tanhf(zg0);
            c0.y = sigf(zf1) * c0.y + sigf(zi1) * tanhf(zg1);
            float2 h0n;
            h0n.x = sigf(zo0) * tanhf(c0.x);
            h0n.y = sigf(zo1) * tanhf(c0.y);
            *(float2*)(&g_h0[(t + 1) & 1][0][0] + (size_t)u * BB + b0) = h0n;
        }

        /* single grid barrier per step (double buffering covers other hazards) */
        grid_barrier(nctas, phase);

        /* ---- layer 1: gates = Wih1 @ h0new + Whh1 @ h1old + b1 ---- */
        const float* h0new = &g_h0[(t + 1) & 1][0][0] + b0;
        const float* h1old = &g_h1[t & 1][0][0] + b0;
        ull bif0 = 0ull, bgo0 = 0ull, bif1 = 0ull, bgo1 = 0ull;
        gemv_pass(h0new, w1s, bif0, bgo0, bif1, bgo1);
        gemv_pass(h1old, w1s + HH, bif0, bgo0, bif1, bgo1);
        {
            float bi = enc ? be[0] : bd[0];
            float bf = enc ? be[1] : bd[1];
            float bg = enc ? be[2] : bd[2];
            float bo = enc ? be[3] : bd[3];
            float2 if0 = unpack2(bif0), go0 = unpack2(bgo0);
            float2 if1 = unpack2(bif1), go1 = unpack2(bgo1);
            float zi0 = if0.x + bi, zf0 = if0.y + bf, zg0 = go0.x + bg, zo0 = go0.y + bo;
            float zi1 = if1.x + bi, zf1 = if1.y + bf, zg1 = go1.x + bg, zo1 = go1.y + bo;
            c1.x = sigf(zf0) * c1.x + sigf(zi0) * tanhf(zg0);
            c1.y = sigf(zf1) * c1.y + sigf(zi1) * tanhf(zg1);
            float2 h1n;
            h1n.x = sigf(zo0) * tanhf(c1.x);
            h1n.y = sigf(zo1) * tanhf(c1.y);
            *(float2*)(&g_h1[(t + 1) & 1][0][0] + (size_t)u * BB + b0) = h1n;
            if (!enc) {
                int col = (t - TT) * BB + b0;
                g_hist[col][u] = h1n.x;
                g_hist[col + 1][u] = h1n.y;
            }
        }
        /* no second barrier: layer-1(t) writes are protected by barrier in step t+1 */
    }
}

/* ---------------- launch ---------------- */
extern "C" void kernel_launch(void* const* d_in, const int* in_sizes, int n_in,
                              void* d_out, int out_size) {
    const void* in[32];
    int j = 0;
    for (int k = 0; k < n_in && j < 32; k++) {
        if (in_sizes[k] == 1) continue;       /* skip scalar src_lens/trg_lens */
        in[j++] = d_in[k];
    }
    const int*   src   = (const int*)in[0];
    const int*   trg   = (const int*)in[1];
    const float* vs    = (const float*)in[2];
    const float* embE  = (const float*)in[3];
    const float* embD  = (const float*)in[4];
    const float* eWih0 = (const float*)in[5];
    const float* eWhh0 = (const float*)in[6];
    const float* eb0   = (const float*)in[7];
    const float* eWih1 = (const float*)in[8];
    const float* eWhh1 = (const float*)in[9];
    const float* eb1   = (const float*)in[10];
    const float* dWih0 = (const float*)in[11];
    const float* dWhh0 = (const float*)in[12];
    const float* db0   = (const float*)in[13];
    const float* dWih1 = (const float*)in[14];
    const float* dWhh1 = (const float*)in[15];
    const float* db1   = (const float*)in[16];
    const float* fcW   = (const float*)in[17];
    const float* fcb   = (const float*)in[18];
    float* out = (float*)d_out;

    static int smem_set = 0;
    if (!smem_set) {
        cudaFuncSetAttribute(rnn_kernel, cudaFuncAttributeMaxDynamicSharedMemorySize,
                             W_SMEM_BYTES);
        smem_set = 1;
    }

    reset_kernel<<<1250, 256>>>(out);
    gather_kernel<<<2048, 256>>>(embE, src, NCOLS_E, 0);
    gather_kernel<<<2032, 256>>>(embD, trg, NCOLS_D, 1);
    repack_kernel<<<512, 256>>>(eWhh0, dWhh0, eWih1, eWhh1, dWih1, dWhh1);

    /* layer-0 input preactivations */
    gemm_kernel<<<dim3(NCOLS_E / 64, 2048 / 64), 256>>>(eWih0, 2048, EE, 0, eb0,
                                                        nullptr, nullptr, nullptr);
    gemm_kernel<<<dim3(NCOLS_D / 64, 2048 / 64), 256>>>(dWih0, 2048, EE, 1, db0,
                                                        nullptr, nullptr, nullptr);
    /* serial recurrence */
    rnn_kernel<<<RNN_CTAS, 128, W_SMEM_BYTES>>>(eb1, db1);
    /* vocab projection + similarity mask */
    gemm_kernel<<<dim3(NCOLS_D / 64, (VV + 63) / 64), 256>>>(fcW, VV, HH, 2, fcb,
                                                             src, vs, out);
}

// round 6
// speedup vs baseline: 3.9109x; 1.5188x over previous
#include <cuda_runtime.h>
#include <cuda_bf16.h>
#include <cstdint>

typedef unsigned long long ull;

#define TT   128
#define BB   64
#define HH   512
#define EE   256
#define VV   5000
#define NSTEP 255          /* 128 enc + 127 dec */
#define NCOLS_E 8192       /* 128*64 */
#define NCOLS_D 8128       /* 127*64 */
#define RNN_CTAS 128
/* smem floats: w0 8192 | w1 16384 | red0 1024 | red1 1024 */
#define RED0_OFF 24576
#define RED1_OFF 25600
#define W_SMEM_FLOATS 26624
#define W_SMEM_BYTES  (W_SMEM_FLOATS * 4)

/* ---------------- device scratch (static, no allocation) ---------------- */
__device__ float g_xe[NCOLS_E][EE];
__device__ float g_xd[NCOLS_D][EE];
__device__ float g_pre_e[TT][HH][BB][4];
__device__ float g_pre_d[TT - 1][HH][BB][4];
__device__ float g_w0e[HH][HH][4];
__device__ float g_w0d[HH][HH][4];
__device__ float g_w1e[HH][2 * HH][4];
__device__ float g_w1d[HH][2 * HH][4];
__device__ float g_h0[2][HH][BB];
__device__ float g_h1[2][HH][BB];
__device__ float g_hist[NCOLS_D][HH];
__device__ unsigned g_count;
__device__ unsigned g_phase;

/* ---------------- f32x2 helpers ---------------- */
__device__ __forceinline__ void fma2(ull& acc, ull a, ull b) {
    asm("fma.rn.f32x2 %0, %1, %2, %0;" : "+l"(acc) : "l"(a), "l"(b));
}
__device__ __forceinline__ ull add2(ull a, ull b) {
    ull r; asm("add.rn.f32x2 %0, %1, %2;" : "=l"(r) : "l"(a), "l"(b));
    return r;
}
__device__ __forceinline__ ull splat2(float x) {
    ull r; unsigned u = __float_as_uint(x);
    asm("mov.b64 %0, {%1, %1};" : "=l"(r) : "r"(u));
    return r;
}
__device__ __forceinline__ float2 unpack2(ull v) {
    unsigned lo, hi;
    asm("mov.b64 {%0, %1}, %2;" : "=r"(lo), "=r"(hi) : "l"(v));
    float2 f; f.x = __uint_as_float(lo); f.y = __uint_as_float(hi);
    return f;
}
__device__ __forceinline__ float sigf(float x) { return 1.0f / (1.0f + __expf(-x)); }

/* ---------------- reset ---------------- */
__global__ void reset_kernel(float* __restrict__ out) {
    int i = blockIdx.x * blockDim.x + threadIdx.x;
    if (i < BB * VV) out[i] = 0.0f;
    if (i < HH * BB) {
        (&g_h0[0][0][0])[i] = 0.0f;
        (&g_h1[0][0][0])[i] = 0.0f;
    }
    if (i == 0) { g_count = 0u; g_phase = 0u; }
}

/* ---------------- embedding gather ---------------- */
__global__ void gather_kernel(const float* __restrict__ emb,
                              const int* __restrict__ tok,
                              int ncols, int dec) {
    int i = blockIdx.x * blockDim.x + threadIdx.x;
    if (i >= ncols * (EE / 4)) return;
    int col = i >> 6;
    int e4  = i & 63;
    float4 v = ((const float4*)emb)[(size_t)tok[col] * 64 + e4];
    float4* dst = dec ? (float4*)&g_xd[0][0] : (float4*)&g_xe[0][0];
    dst[(size_t)col * 64 + e4] = v;
}

/* ---------------- weight repack ---------------- */
__global__ void repack_kernel(const float* __restrict__ eWhh0, const float* __restrict__ dWhh0,
                              const float* __restrict__ eWih1, const float* __restrict__ eWhh1,
                              const float* __restrict__ dWih1, const float* __restrict__ dWhh1) {
    int stride = gridDim.x * blockDim.x;
    int idx = blockIdx.x * blockDim.x + threadIdx.x;
    for (int i = idx; i < HH * HH; i += stride) {
        int u = i / HH, k = i % HH;
        #pragma unroll
        for (int g = 0; g < 4; g++) {
            g_w0e[u][k][g] = eWhh0[(size_t)(g * HH + u) * HH + k];
            g_w0d[u][k][g] = dWhh0[(size_t)(g * HH + u) * HH + k];
        }
    }
    for (int i = idx; i < HH * 2 * HH; i += stride) {
        int u = i / (2 * HH), k = i % (2 * HH);
        #pragma unroll
        for (int g = 0; g < 4; g++) {
            float ve, vd;
            if (k < HH) { ve = eWih1[(size_t)(g * HH + u) * HH + k];
                          vd = dWih1[(size_t)(g * HH + u) * HH + k]; }
            else        { ve = eWhh1[(size_t)(g * HH + u) * HH + (k - HH)];
                          vd = dWhh1[(size_t)(g * HH + u) * HH + (k - HH)]; }
            g_w1e[u][k][g] = ve;
            g_w1d[u][k][g] = vd;
        }
    }
}

/* ---------------- generic 64x64 tiled fp32 GEMM, C = A(MxK) * B(NxK)^T ---------------- */
__global__ void __launch_bounds__(256) gemm_kernel(
    const float* __restrict__ A, int M, int K, int mode,
    const float* __restrict__ bias,
    const int* __restrict__ src, const float* __restrict__ vs,
    float* __restrict__ outp) {
    __shared__ float As[32][64];
    __shared__ float Bs[32][64];

    const float* B = (mode == 0) ? &g_xe[0][0] : (mode == 1) ? &g_xd[0][0] : &g_hist[0][0];

    int tid = threadIdx.x;
    int r = (tid & 15) << 2;
    int c = (tid >> 4) << 2;
    int m0 = blockIdx.y * 64;
    int n0 = blockIdx.x * 64;

    ull acc[4][2];
    #pragma unroll
    for (int i = 0; i < 4; i++) { acc[i][0] = 0ull; acc[i][1] = 0ull; }

    for (int kt = 0; kt < K; kt += 32) {
        #pragma unroll
        for (int rep = 0; rep < 2; rep++) {
            int f = tid + rep * 256;
            int m = f >> 3;
            int k4 = (f & 7) << 2;
            int gm = m0 + m;
            float4 va = make_float4(0.f, 0.f, 0.f, 0.f);
            if (gm < M) va = *(const float4*)&A[(size_t)gm * K + kt + k4];
            As[k4 + 0][m] = va.x; As[k4 + 1][m] = va.y;
            As[k4 + 2][m] = va.z; As[k4 + 3][m] = va.w;
            float4 vb = *(const float4*)&B[(size_t)(n0 + m) * K + kt + k4];
            Bs[k4 + 0][m] = vb.x; Bs[k4 + 1][m] = vb.y;
            Bs[k4 + 2][m] = vb.z; Bs[k4 + 3][m] = vb.w;
        }
        __syncthreads();
        #pragma unroll
        for (int k = 0; k < 32; k++) {
            float4 av = *(const float4*)&As[k][r];
            float4 bv = *(const float4*)&Bs[k][c];
            ull b01 = ((const ull*)&bv)[0];
            ull b23 = ((const ull*)&bv)[1];
            ull a0 = splat2(av.x), a1 = splat2(av.y), a2 = splat2(av.z), a3 = splat2(av.w);
            fma2(acc[0][0], a0, b01); fma2(acc[0][1], a0, b23);
            fma2(acc[1][0], a1, b01); fma2(acc[1][1], a1, b23);
            fma2(acc[2][0], a2, b01); fma2(acc[2][1], a2, b23);
            fma2(acc[3][0], a3, b01); fma2(acc[3][1], a3, b23);
        }
        __syncthreads();
    }

    #pragma unroll
    for (int i = 0; i < 4; i++) {
        int m = m0 + r + i;
        if (m >= M) continue;
        float bval = bias[m];
        float2 v01 = unpack2(acc[i][0]);
        float2 v23 = unpack2(acc[i][1]);
        float vals[4] = { v01.x + bval, v01.y + bval, v23.x + bval, v23.y + bval };
        #pragma unroll
        for (int j = 0; j < 4; j++) {
            int n = n0 + c + j;
            if (mode == 2) {
                int s0 = src[n], s1 = src[n + 64];
                float sim = fminf(vs[(size_t)s0 * VV + m], vs[(size_t)s1 * VV + m]);
                float md = fminf(sim, 20.0f);
                float mult = (m == 3 || m == 4 || m == VV - 1) ? 1.0f
                                                               : (md * md - 20.0f * md + 1.0f);
                outp[(size_t)(n + 64) * VV + m] = vals[j] * mult;
            } else {
                int t = n >> 6, b = n & 63;
                int uu = m & 511, g = m >> 9;
                float* dst = (mode == 0) ? &g_pre_e[0][0][0][0] : &g_pre_d[0][0][0][0];
                dst[(((size_t)t * HH + uu) * BB + b) * 4 + g] = vals[j];
            }
        }
    }
}

/* ---------------- grid barrier ---------------- */
__device__ __forceinline__ void grid_barrier(unsigned nctas, unsigned& local_phase) {
    __syncthreads();
    if (threadIdx.x == 0) {
        unsigned target = local_phase + 1u;
        __threadfence();
        unsigned old = atomicAdd(&g_count, 1u);
        if (old == nctas - 1u) {
            g_count = 0u;
            __threadfence();
            atomicExch(&g_phase, target);
        } else {
            while (*(volatile unsigned*)&g_phase < target) { }
            __threadfence();
        }
    }
    local_phase++;
    __syncthreads();
}

/* ---------------- software-pipelined GEMV over cnt k values ---------------- */
__device__ __forceinline__ void gemv_pass(const float* __restrict__ hbase,
                                          const ulonglong2* __restrict__ wbase,
                                          int cnt,
                                          ull& aif0, ull& ago0, ull& aif1, ull& ago1) {
    float2 bufA[16], bufB[16];
    #pragma unroll
    for (int i = 0; i < 16; i++)
        bufA[i] = *(const float2*)(hbase + (size_t)i * BB);

    #pragma unroll 1
    for (int k = 0; k < cnt; k += 32) {
        #pragma unroll
        for (int i = 0; i < 16; i++)
            bufB[i] = *(const float2*)(hbase + (size_t)(k + 16 + i) * BB);
        #pragma unroll
        for (int i = 0; i < 16; i++) {
            ulonglong2 w = wbase[k + i];
            ull ha = splat2(bufA[i].x), hb = splat2(bufA[i].y);
            fma2(aif0, ha, w.x); fma2(ago0, ha, w.y);
            fma2(aif1, hb, w.x); fma2(ago1, hb, w.y);
        }
        int kn = (k + 32 < cnt) ? (k + 32) : 0;   /* harmless wrap prefetch */
        #pragma unroll
        for (int i = 0; i < 16; i++)
            bufA[i] = *(const float2*)(hbase + (size_t)(kn + i) * BB);
        #pragma unroll
        for (int i = 0; i < 16; i++) {
            ulonglong2 w = wbase[k + 16 + i];
            ull ha = splat2(bufB[i].x), hb = splat2(bufB[i].y);
            fma2(aif0, ha, w.x); fma2(ago0, ha, w.y);
            fma2(aif1, hb, w.x); fma2(ago1, hb, w.y);
        }
    }
}

/* ---------------- persistent LSTM recurrence: 256 thr, 2 warps/SMSP ----------------
   warps 0-3 (group A): own unit usub = warp, lanes = batch pairs; do epilogues.
   warps 4-7 (group B): same (u, b) map; second half of the k work.
   Layer 0: A takes k[0,256), B takes k[256,512)        -> reduce in smem red0.
   Layer 1: A takes h0new pass, B takes h1old pass      -> reduce in smem red1. */
__global__ void __launch_bounds__(256, 1) rnn_kernel(const float* __restrict__ eb1,
                                                     const float* __restrict__ db1) {
    extern __shared__ float s_w[];
    const int tid  = threadIdx.x;
    const int lane = tid & 31;
    const int warp = tid >> 5;
    const int grp  = warp >> 2;             /* 0 = A, 1 = B                    */
    const int usub = warp & 3;
    const int u = blockIdx.x * 4 + usub;
    const int b0 = lane * 2;
    const int slot = (tid & 127);           /* matching (usub, lane) slot       */
    const unsigned nctas = gridDim.x;
    unsigned phase = 0;

    ull* red0 = (ull*)&s_w[RED0_OFF];
    ull* red1 = (ull*)&s_w[RED1_OFF];

    float2 c0 = make_float2(0.f, 0.f);
    float2 c1 = make_float2(0.f, 0.f);

    float be[4], bd[4];
    #pragma unroll
    for (int g = 0; g < 4; g++) { be[g] = eb1[g * HH + u]; bd[g] = db1[g * HH + u]; }

    const ulonglong2* w0s = (const ulonglong2*)&s_w[usub * 2048];          /* [512]  */
    const ulonglong2* w1s = (const ulonglong2*)&s_w[8192 + usub * 4096];   /* [1024] */

    for (int t = 0; t < NSTEP; t++) {
        const bool enc = (t < TT);

        if (t == 0 || t == TT) {
            const float4* src0 = (const float4*)(enc ? &g_w0e[blockIdx.x * 4][0][0]
                                                     : &g_w0d[blockIdx.x * 4][0][0]);
            const float4* src1 = (const float4*)(enc ? &g_w1e[blockIdx.x * 4][0][0]
                                                     : &g_w1d[blockIdx.x * 4][0][0]);
            float4* d0 = (float4*)s_w;
            float4* d1 = (float4*)(s_w + 8192);
            for (int i = tid; i < 2048; i += 256) d0[i] = src0[i];
            for (int i = tid; i < 4096; i += 256) d1[i] = src1[i];
            __syncthreads();
        }

        /* ---- layer 0: gates = pre[t] + Whh0 @ h0old, k split A/B ---- */
        const float* h0old = &g_h0[t & 1][0][0] + b0;
        ull aif0 = 0ull, ago0 = 0ull, aif1 = 0ull, ago1 = 0ull;
        if (grp == 0) {
            gemv_pass(h0old, w0s, 256, aif0, ago0, aif1, ago1);
        } else {
            gemv_pass(h0old + 256 * BB, w0s + 256, 256, aif0, ago0, aif1, ago1);
            red0[slot * 4 + 0] = aif0; red0[slot * 4 + 1] = ago0;
            red0[slot * 4 + 2] = aif1; red0[slot * 4 + 3] = ago1;
        }
        __syncthreads();
        if (grp == 0) {
            aif0 = add2(aif0, red0[slot * 4 + 0]);
            ago0 = add2(ago0, red0[slot * 4 + 1]);
            aif1 = add2(aif1, red0[slot * 4 + 2]);
            ago1 = add2(ago1, red0[slot * 4 + 3]);
            const float4* pre4 = enc ? (const float4*)&g_pre_e[t][u][0][0]
                                     : (const float4*)&g_pre_d[t - TT][u][0][0];
            float4 p0 = pre4[b0];
            float4 p1 = pre4[b0 + 1];
            float2 if0 = unpack2(aif0), go0 = unpack2(ago0);
            float2 if1 = unpack2(aif1), go1 = unpack2(ago1);
            float zi0 = if0.x + p0.x, zf0 = if0.y + p0.y, zg0 = go0.x + p0.z, zo0 = go0.y + p0.w;
            float zi1 = if1.x + p1.x, zf1 = if1.y + p1.y, zg1 = go1.x + p1.z, zo1 = go1.y + p1.w;
            c0.x = sigf(zf0) * c0.x + sigf(zi0) * tanhf(zg0);
            c0.y = sigf(zf1) * c0.y + sigf(zi1) * tanhf(zg1);
            float2 h0n;
            h0n.x = sigf(zo0) * tanhf(c0.x);
            h0n.y = sigf(zo1) * tanhf(c0.y);
            *(float2*)(&g_h0[(t + 1) & 1][0][0] + (size_t)u * BB + b0) = h0n;
        }

        grid_barrier(nctas, phase);

        /* ---- layer 1: A does Wih1@h0new, B does Whh1@h1old ---- */
        ull bif0 = 0ull, bgo0 = 0ull, bif1 = 0ull, bgo1 = 0ull;
        if (grp == 0) {
            const float* h0new = &g_h0[(t + 1) & 1][0][0] + b0;
            gemv_pass(h0new, w1s, 512, bif0, bgo0, bif1, bgo1);
        } else {
            const float* h1old = &g_h1[t & 1][0][0] + b0;
            gemv_pass(h1old, w1s + HH, 512, bif0, bgo0, bif1, bgo1);
            red1[slot * 4 + 0] = bif0; red1[slot * 4 + 1] = bgo0;
            red1[slot * 4 + 2] = bif1; red1[slot * 4 + 3] = bgo1;
        }
        __syncthreads();
        if (grp == 0) {
            bif0 = add2(bif0, red1[slot * 4 + 0]);
            bgo0 = add2(bgo0, red1[slot * 4 + 1]);
            bif1 = add2(bif1, red1[slot * 4 + 2]);
            bgo1 = add2(bgo1, red1[slot * 4 + 3]);
            float bi = enc ? be[0] : bd[0];
            float bf = enc ? be[1] : bd[1];
            float bg = enc ? be[2] : bd[2];
            float bo = enc ? be[3] : bd[3];
            float2 if0 = unpack2(bif0), go0 = unpack2(bgo0);
            float2 if1 = unpack2(bif1), go1 = unpack2(bgo1);
            float zi0 = if0.x + bi, zf0 = if0.y + bf, zg0 = go0.x + bg, zo0 = go0.y + bo;
            float zi1 = if1.x + bi, zf1 = if1.y + bf, zg1 = go1.x + bg, zo1 = go1.y + bo;
            c1.x = sigf(zf0) * c1.x + sigf(zi0) * tanhf(zg0);
            c1.y = sigf(zf1) * c1.y + sigf(zi1) * tanhf(zg1);
            float2 h1n;
            h1n.x = sigf(zo0) * tanhf(c1.x);
            h1n.y = sigf(zo1) * tanhf(c1.y);
            *(float2*)(&g_h1[(t + 1) & 1][0][0] + (size_t)u * BB + b0) = h1n;
            if (!enc) {
                int col = (t - TT) * BB + b0;
                g_hist[col][u] = h1n.x;
                g_hist[col + 1][u] = h1n.y;
            }
        }
        /* layer-1(t) writes are protected by the grid barrier inside step t+1 */
    }
}

/* ---------------- launch ---------------- */
extern "C" void kernel_launch(void* const* d_in, const int* in_sizes, int n_in,
                              void* d_out, int out_size) {
    const void* in[32];
    int j = 0;
    for (int k = 0; k < n_in && j < 32; k++) {
        if (in_sizes[k] == 1) continue;       /* skip scalar src_lens/trg_lens */
        in[j++] = d_in[k];
    }
    const int*   src   = (const int*)in[0];
    const int*   trg   = (const int*)in[1];
    const float* vs    = (const float*)in[2];
    const float* embE  = (const float*)in[3];
    const float* embD  = (const float*)in[4];
    const float* eWih0 = (const float*)in[5];
    const float* eWhh0 = (const float*)in[6];
    const float* eb0   = (const float*)in[7];
    const float* eWih1 = (const float*)in[8];
    const float* eWhh1 = (const float*)in[9];
    const float* eb1   = (const float*)in[10];
    const float* dWih0 = (const float*)in[11];
    const float* dWhh0 = (const float*)in[12];
    const float* db0   = (const float*)in[13];
    const float* dWih1 = (const float*)in[14];
    const float* dWhh1 = (const float*)in[15];
    const float* db1   = (const float*)in[16];
    const float* fcW   = (const float*)in[17];
    const float* fcb   = (const float*)in[18];
    float* out = (float*)d_out;

    static int smem_set = 0;
    if (!smem_set) {
        cudaFuncSetAttribute(rnn_kernel, cudaFuncAttributeMaxDynamicSharedMemorySize,
                             W_SMEM_BYTES);
        smem_set = 1;
    }

    reset_kernel<<<1250, 256>>>(out);
    gather_kernel<<<2048, 256>>>(embE, src, NCOLS_E, 0);
    gather_kernel<<<2032, 256>>>(embD, trg, NCOLS_D, 1);
    repack_kernel<<<512, 256>>>(eWhh0, dWhh0, eWih1, eWhh1, dWih1, dWhh1);

    gemm_kernel<<<dim3(NCOLS_E / 64, 2048 / 64), 256>>>(eWih0, 2048, EE, 0, eb0,
                                                        nullptr, nullptr, nullptr);
    gemm_kernel<<<dim3(NCOLS_D / 64, 2048 / 64), 256>>>(dWih0, 2048, EE, 1, db0,
                                                        nullptr, nullptr, nullptr);
    rnn_kernel<<<RNN_CTAS, 256, W_SMEM_BYTES>>>(eb1, db1);
    gemm_kernel<<<dim3(NCOLS_D / 64, (VV + 63) / 64), 256>>>(fcW, VV, HH, 2, fcb,
                                                             src, vs, out);
}